// round 5
// baseline (speedup 1.0000x reference)
#include <cuda_runtime.h>
#include <cuda_bf16.h>
#include <cstdint>

// ---------------- problem constants ----------------
#define N_ROWS   16384
#define N_CODES  8192
#define DIM      512
#define Q_ELEMS  (N_ROWS * DIM)

// ---------------- GEMM tiling (fp8) ----------------
#define BM 128
#define BN 128
#define KCB 128               // K bytes (= fp8 elems) per stage, 128 B per row
#define NSTAGES (DIM / KCB)   // 4
#define NPIPE 3
#define CH 8                  // codes per argmin chunk
#define NCH (N_CODES / CH)    // 1024 chunk-mins per row
#define EPS 2.0e-3f
#define ESCALE 8192.0f
#define DSCALE (2.0f / 8192.0f)

// dynamic smem: 3 stages x (A 16KB + B 16KB) = 98304, enorm after
#define STG_BYTES 32768
#define SM_BOFF   16384
#define SM_ENORM  98304
#define SM_TOTAL  (98304 + 512)

// ---------------- scratch (device globals; no allocation allowed) ----------------
__device__ __align__(256) uint8_t g_qx[(size_t)N_ROWS * DIM];   // e4m3(x)
__device__ __align__(256) uint8_t g_qe[(size_t)N_CODES * DIM];  // e4m3(emb*8192)
__device__ float g_xnorm[N_ROWS];
__device__ float g_enorm[N_CODES];
__device__ float g_cmin[(size_t)N_ROWS * NCH];
__device__ float g_rowsq[N_ROWS];
__device__ int   g_bestidx[N_ROWS];
__device__ int   g_maxidx;

// ---------------- PTX helpers ----------------
__device__ __forceinline__ uint32_t smem_u32(const void* p) {
    uint32_t a;
    asm("{ .reg .u64 t; cvta.to.shared.u64 t, %1; cvt.u32.u64 %0, t; }"
        : "=r"(a) : "l"(p));
    return a;
}
__device__ __forceinline__ void cp16(uint32_t dst, const void* src) {
    asm volatile("cp.async.cg.shared.global [%0], [%1], 16;" :: "r"(dst), "l"(src) : "memory");
}
#define CP_COMMIT() asm volatile("cp.async.commit_group;" ::: "memory")
#define CP_WAIT(n)  asm volatile("cp.async.wait_group %0;" :: "n"(n) : "memory")

#define SWZ(b) ((b) ^ (((b) >> 3) & 0x70))

__device__ __forceinline__ void ldsm4(uint32_t* r, uint32_t addr) {
    asm volatile("ldmatrix.sync.aligned.m8n8.x4.shared.b16 {%0,%1,%2,%3}, [%4];"
                 : "=r"(r[0]), "=r"(r[1]), "=r"(r[2]), "=r"(r[3]) : "r"(addr));
}
__device__ __forceinline__ void mma_fp8(float* c, const uint32_t* a, const uint32_t* b) {
    asm volatile(
        "mma.sync.aligned.m16n8k32.row.col.f32.e4m3.e4m3.f32 "
        "{%0,%1,%2,%3}, {%4,%5,%6,%7}, {%8,%9}, {%0,%1,%2,%3};"
        : "+f"(c[0]), "+f"(c[1]), "+f"(c[2]), "+f"(c[3])
        : "r"(a[0]), "r"(a[1]), "r"(a[2]), "r"(a[3]), "r"(b[0]), "r"(b[1]));
}
__device__ __forceinline__ uint32_t pack_e4m3x4(float v0, float v1, float v2, float v3) {
    uint16_t h0, h1;
    asm("cvt.rn.satfinite.e4m3x2.f32 %0, %1, %2;" : "=h"(h0) : "f"(v1), "f"(v0));
    asm("cvt.rn.satfinite.e4m3x2.f32 %0, %1, %2;" : "=h"(h1) : "f"(v3), "f"(v2));
    return (uint32_t)h0 | ((uint32_t)h1 << 16);
}

// ---------------- kernels ----------------
__global__ void init_kernel() { g_maxidx = 0; }

// one warp per row: fp32 norm + e4m3 convert (emb scaled by 8192)
__global__ void convert_kernel(const float* __restrict__ x, const float* __restrict__ emb) {
    int warp = (blockIdx.x * blockDim.x + threadIdx.x) >> 5;
    int lane = threadIdx.x & 31;
    const float* src; uint8_t* dst; float* nrm; int row; float sc;
    if (warp < N_ROWS) { src = x; dst = g_qx; nrm = g_xnorm; row = warp; sc = 1.0f; }
    else               { src = emb; dst = g_qe; nrm = g_enorm; row = warp - N_ROWS; sc = ESCALE; }
    const float4* p = reinterpret_cast<const float4*>(src + (size_t)row * DIM);
    uint32_t* o = reinterpret_cast<uint32_t*>(dst + (size_t)row * DIM);
    float s = 0.f;
    #pragma unroll
    for (int c = lane; c < DIM / 4; c += 32) {
        float4 v = p[c];
        s += v.x * v.x + v.y * v.y + v.z * v.z + v.w * v.w;
        o[c] = pack_e4m3x4(v.x * sc, v.y * sc, v.z * sc, v.w * sc);
    }
    #pragma unroll
    for (int off = 16; off; off >>= 1) s += __shfl_xor_sync(0xffffffffu, s, off);
    if (lane == 0) nrm[row] = s;
}

// fast e4m3 HMMA GEMM: per CTA 128 rows x 128 codes x K=512, 256 thr, 3-stage, 2 CTA/SM.
// Epilogue: d~ = enorm - (2/8192)*dot, per-row min over 8-code chunks -> g_cmin.
__global__ void __launch_bounds__(256, 2) vq_gemm_kernel() {
    extern __shared__ __align__(1024) char smem[];
    const int tid = threadIdx.x;
    const int w = tid >> 5, l = tid & 31;
    const int rowBase = blockIdx.x * BM;
    const int cb = blockIdx.y * BN;
    const uint32_t sb = smem_u32(smem);
    float* senorm = reinterpret_cast<float*>(smem + SM_ENORM);

    if (tid < BN) senorm[tid] = g_enorm[cb + tid];

    // warp layout: 2 (M) x 4 (N); warp tile 64 x 32
    const int m0 = (w >> 2) * 64;
    const int n0 = (w & 3) * 32;

    const int aRowLane = l & 15;
    const int aChunkHi = l >> 4;
    const int bRowLane = ((l >> 4) & 1) * 8 + (l & 7);
    const int bChunkHi = (l >> 3) & 1;

    float c[4][4][4];
    #pragma unroll
    for (int mt = 0; mt < 4; mt++)
        #pragma unroll
        for (int nt = 0; nt < 4; nt++)
            #pragma unroll
            for (int e = 0; e < 4; e++) c[mt][nt][e] = 0.f;

    // stage loader: K byte-chunk kc*128 -> stage s (rows are 128 B of fp8)
    auto load_stage = [&](int kc, int s) {
        const int kb = kc * KCB;
        const uint32_t stg = sb + (uint32_t)s * STG_BYTES;
        #pragma unroll
        for (int q = 0; q < 4; q++) {            // A: 128 rows x 8 x 16B
            int t = tid + q * 256;
            int r = t >> 3, ch = t & 7;
            cp16(stg + SWZ((uint32_t)(r * 128 + ch * 16)),
                 g_qx + (size_t)(rowBase + r) * DIM + kb + ch * 16);
        }
        #pragma unroll
        for (int q = 0; q < 4; q++) {            // B: 128 rows x 8 x 16B
            int t = tid + q * 256;
            int r = t >> 3, ch = t & 7;
            cp16(stg + SM_BOFF + SWZ((uint32_t)(r * 128 + ch * 16)),
                 g_qe + (size_t)(cb + r) * DIM + kb + ch * 16);
        }
        CP_COMMIT();
    };

    load_stage(0, 0);
    load_stage(1, 1);
    load_stage(2, 2);

    int buf = 0;
    for (int i = 0; i < NSTAGES; i++) {
        CP_WAIT(2);
        __syncthreads();
        const uint32_t aStg = sb + (uint32_t)buf * STG_BYTES;
        const uint32_t bStg = aStg + SM_BOFF;
        #pragma unroll
        for (int ks = 0; ks < 4; ks++) {         // 4 x K32 per 128B stage
            uint32_t a[4][4], b[4][2];
            #pragma unroll
            for (int mt = 0; mt < 4; mt++) {
                uint32_t off = (uint32_t)((m0 + mt * 16 + aRowLane) * 128
                                          + (ks * 2 + aChunkHi) * 16);
                ldsm4(a[mt], aStg + SWZ(off));
            }
            #pragma unroll
            for (int nt2 = 0; nt2 < 2; nt2++) {
                uint32_t r4[4];
                uint32_t off = (uint32_t)((n0 + nt2 * 16 + bRowLane) * 128
                                          + (ks * 2 + bChunkHi) * 16);
                ldsm4(r4, bStg + SWZ(off));
                b[nt2 * 2][0] = r4[0]; b[nt2 * 2][1] = r4[1];
                b[nt2 * 2 + 1][0] = r4[2]; b[nt2 * 2 + 1][1] = r4[3];
            }
            #pragma unroll
            for (int mt = 0; mt < 4; mt++)
                #pragma unroll
                for (int nt = 0; nt < 4; nt++)
                    mma_fp8(c[mt][nt], a[mt], b[nt]);
        }
        __syncthreads();
        if (i + NPIPE < NSTAGES) load_stage(i + NPIPE, buf);
        else CP_COMMIT();                        // keep wait-depth invariant at drain
        buf = (buf + 1 == NPIPE) ? 0 : buf + 1;
    }

    // ---- epilogue: chunk (8-code) mins -> smem staging -> coalesced gmem
    __syncthreads();
    float* sbuf = reinterpret_cast<float*>(smem);   // [128][20]

    const int j0 = (l & 3) * 2;
    #pragma unroll
    for (int mt = 0; mt < 4; mt++) {
        #pragma unroll
        for (int nt = 0; nt < 4; nt++) {
            const int colBase = n0 + nt * 8 + j0;
            float en0 = senorm[colBase], en1 = senorm[colBase + 1];
            float v0 = fminf(en0 - DSCALE * c[mt][nt][0], en1 - DSCALE * c[mt][nt][1]);
            float v1 = fminf(en0 - DSCALE * c[mt][nt][2], en1 - DSCALE * c[mt][nt][3]);
            #pragma unroll
            for (int off = 1; off <= 2; off <<= 1) {
                v0 = fminf(v0, __shfl_xor_sync(0xffffffffu, v0, off));
                v1 = fminf(v1, __shfl_xor_sync(0xffffffffu, v1, off));
            }
            if ((l & 3) == 0) {
                int rloc = m0 + mt * 16 + (l >> 2);
                int chLoc = (w & 3) * 4 + nt;
                sbuf[rloc * 20 + chLoc] = v0;
                sbuf[(rloc + 8) * 20 + chLoc] = v1;
            }
        }
    }
    __syncthreads();
    {
        int row = tid >> 1, half = tid & 1;
        const float* s = &sbuf[row * 20 + half * 8];
        float4 o0 = make_float4(s[0], s[1], s[2], s[3]);
        float4 o1 = make_float4(s[4], s[5], s[6], s[7]);
        float* dst = &g_cmin[(size_t)(rowBase + row) * NCH + blockIdx.y * 16 + half * 8];
        reinterpret_cast<float4*>(dst)[0] = o0;
        reinterpret_cast<float4*>(dst)[1] = o1;
    }
}

// warp-per-row exact argmin: scan chunk mins, rescore candidate chunks with
// 4 lanes per code (8 codes of a chunk in parallel). grid N_ROWS/8, block 256.
__global__ void __launch_bounds__(256) argmin_kernel(const float* __restrict__ x,
                                                     const float* __restrict__ emb,
                                                     float* __restrict__ out) {
    __shared__ __align__(16) float sx[8][DIM];
    const int wrp = threadIdx.x >> 5, lane = threadIdx.x & 31;
    const int row = blockIdx.x * 8 + wrp;

    const float4* x4 = reinterpret_cast<const float4*>(x + (size_t)row * DIM);
    float4* sx4 = reinterpret_cast<float4*>(sx[wrp]);
    #pragma unroll
    for (int t = 0; t < 4; t++) sx4[t * 32 + lane] = x4[t * 32 + lane];
    __syncwarp();

    const float4* cm4 = reinterpret_cast<const float4*>(&g_cmin[(size_t)row * NCH]);
    float4 cv[8];
    float lmin = 3.4028235e38f;
    #pragma unroll
    for (int q = 0; q < 8; q++) {
        cv[q] = cm4[q * 32 + lane];
        lmin = fminf(fminf(fminf(lmin, cv[q].x), fminf(cv[q].y, cv[q].z)), cv[q].w);
    }
    #pragma unroll
    for (int off = 16; off; off >>= 1) lmin = fminf(lmin, __shfl_xor_sync(0xffffffffu, lmin, off));
    const float thr = lmin + EPS;

    const float xn = g_xnorm[row];
    const int cc8 = lane >> 2, p = lane & 3;
    float bestd = 3.4028235e38f;
    int besti = 0x7fffffff;

    #pragma unroll
    for (int q = 0; q < 8; q++) {
        #pragma unroll
        for (int e = 0; e < 4; e++) {
            float ve = (&cv[q].x)[e];
            unsigned m = __ballot_sync(0xffffffffu, ve <= thr);
            while (m) {
                int b = __ffs(m) - 1;
                m &= m - 1;
                int ci = (q * 32 + b) * 4 + e;
                int code = ci * CH + cc8;
                const float4* e4 = reinterpret_cast<const float4*>(emb + (size_t)code * DIM) + p * 32;
                const float4* xs = sx4 + p * 32;
                float acc = 0.f;
                #pragma unroll
                for (int t = 0; t < 32; t++) {
                    float4 ev = e4[t];
                    float4 xv = xs[t];
                    acc = fmaf(ev.x, xv.x, acc);
                    acc = fmaf(ev.y, xv.y, acc);
                    acc = fmaf(ev.z, xv.z, acc);
                    acc = fmaf(ev.w, xv.w, acc);
                }
                acc += __shfl_xor_sync(0xffffffffu, acc, 1);
                acc += __shfl_xor_sync(0xffffffffu, acc, 2);
                float d; int id;
                if (p == 0) {
                    d = __fsub_rn(__fadd_rn(xn, g_enorm[code]), 2.0f * acc);
                    id = code;
                } else { d = 3.4028235e38f; id = 0x7fffffff; }
                #pragma unroll
                for (int off = 4; off <= 16; off <<= 1) {
                    float od = __shfl_xor_sync(0xffffffffu, d, off);
                    int   oi = __shfl_xor_sync(0xffffffffu, id, off);
                    if (od < d || (od == d && oi < id)) { d = od; id = oi; }
                }
                #pragma unroll
                for (int off = 1; off <= 2; off <<= 1) {
                    float od = __shfl_xor_sync(0xffffffffu, d, off);
                    int   oi = __shfl_xor_sync(0xffffffffu, id, off);
                    if (od < d || (od == d && oi < id)) { d = od; id = oi; }
                }
                if (d < bestd || (d == bestd && id < besti)) { bestd = d; besti = id; }
            }
        }
    }

    if (lane == 0) {
        g_bestidx[row] = besti;
        out[Q_ELEMS + 2 + row] = (float)besti;
        atomicMax(&g_maxidx, besti);
    }
}

// pure streaming: gather + straight-through + rowsq. warp per row.
__global__ void __launch_bounds__(256) gather_kernel(const float* __restrict__ x,
                                                     const float* __restrict__ emb,
                                                     float* __restrict__ out) {
    const int lane = threadIdx.x & 31;
    const int row = blockIdx.x * 8 + (threadIdx.x >> 5);
    const int idx = g_bestidx[row];

    const float4* x4 = reinterpret_cast<const float4*>(x + (size_t)row * DIM);
    const float4* q4 = reinterpret_cast<const float4*>(emb + (size_t)idx * DIM);
    float4* o4 = reinterpret_cast<float4*>(out + (size_t)row * DIM);
    float ss = 0.f;
    #pragma unroll
    for (int t = 0; t < 4; t++) {
        float4 xv = x4[t * 32 + lane];
        float4 qv = q4[t * 32 + lane];
        float4 ov;
        float d0 = __fsub_rn(qv.x, xv.x); ov.x = __fadd_rn(xv.x, d0); ss += d0 * d0;
        float d1 = __fsub_rn(qv.y, xv.y); ov.y = __fadd_rn(xv.y, d1); ss += d1 * d1;
        float d2 = __fsub_rn(qv.z, xv.z); ov.z = __fadd_rn(xv.z, d2); ss += d2 * d2;
        float d3 = __fsub_rn(qv.w, xv.w); ov.w = __fadd_rn(xv.w, d3); ss += d3 * d3;
        o4[t * 32 + lane] = ov;
    }
    #pragma unroll
    for (int off = 16; off; off >>= 1) ss += __shfl_xor_sync(0xffffffffu, ss, off);
    if (lane == 0) g_rowsq[row] = ss;
}

__global__ void scalars_kernel(float* __restrict__ out) {
    __shared__ float red[1024];
    const int tid = threadIdx.x;
    float s = 0.f;
    for (int r = tid; r < N_ROWS; r += 1024) s += g_rowsq[r];
    red[tid] = s;
    __syncthreads();
    #pragma unroll
    for (int st = 512; st > 0; st >>= 1) {
        if (tid < st) red[tid] += red[tid + st];
        __syncthreads();
    }
    if (tid == 0) {
        float mean = red[0] / (float)Q_ELEMS;
        out[Q_ELEMS] = 1.25f * mean;
        float L = (float)(g_maxidx + 1);
        float avg = 1.0f / L;
        out[Q_ELEMS + 1] = expf(-avg * logf(avg + 1e-10f));
    }
}

extern "C" void kernel_launch(void* const* d_in, const int* in_sizes, int n_in,
                              void* d_out, int out_size) {
    const float* x   = (const float*)d_in[0];
    const float* emb = (const float*)d_in[1];
    float* out = (float*)d_out;

    cudaFuncSetAttribute(vq_gemm_kernel, cudaFuncAttributeMaxDynamicSharedMemorySize, SM_TOTAL);

    init_kernel<<<1, 1>>>();
    convert_kernel<<<(N_ROWS + N_CODES) / 8, 256>>>(x, emb);
    vq_gemm_kernel<<<dim3(N_ROWS / BM, N_CODES / BN), 256, SM_TOTAL>>>();
    argmin_kernel<<<N_ROWS / 8, 256>>>(x, emb, out);
    gather_kernel<<<N_ROWS / 8, 256>>>(x, emb, out);
    scalars_kernel<<<1, 1024>>>(out);
}

// round 6
// speedup vs baseline: 2.0416x; 2.0416x over previous
#include <cuda_runtime.h>
#include <cuda_bf16.h>
#include <cstdint>

// ---------------- problem constants ----------------
#define N_ROWS   16384
#define N_CODES  8192
#define DIM      512
#define Q_ELEMS  (N_ROWS * DIM)

// ---------------- GEMM tiling (fp8) ----------------
#define BM 128
#define BN 128
#define KCB 128               // K bytes (= fp8 elems) per stage per row
#define NSTAGES (DIM / KCB)   // 4
#define TILE_BYTES 16384      // 128 rows x 128 B, pre-swizzled
#define CH 8                  // codes per argmin chunk
#define NCH (N_CODES / CH)    // 1024 chunk-mins per row
#define EPS 2.0e-3f
#define ESCALE 8192.0f
#define DSCALE (2.0f / 8192.0f)

// dynamic smem: 3 stages x (A 16KB + B 16KB) = 98304; enorm; mbar[3]
#define STG_BYTES 32768
#define SM_BOFF   16384
#define SM_ENORM  98304
#define SM_MBAR   98816
#define SM_TOTAL  98944

// ---------------- scratch (device globals; no allocation allowed) ----------------
// tile-major pre-swizzled fp8: tile (rb, kc) at ((rb*NSTAGES + kc) << 14)
__device__ __align__(256) uint8_t g_qx[(size_t)N_ROWS * DIM];
__device__ __align__(256) uint8_t g_qe[(size_t)N_CODES * DIM];
__device__ float g_xnorm[N_ROWS];
__device__ float g_enorm[N_CODES];
__device__ float g_cmin[(size_t)N_ROWS * NCH];
__device__ float g_rowsq[N_ROWS];
__device__ int   g_maxidx;

// ---------------- PTX helpers ----------------
__device__ __forceinline__ uint32_t smem_u32(const void* p) {
    uint32_t a;
    asm("{ .reg .u64 t; cvta.to.shared.u64 t, %1; cvt.u32.u64 %0, t; }"
        : "=r"(a) : "l"(p));
    return a;
}
#define SWZ(b) ((b) ^ (((b) >> 3) & 0x70))

__device__ __forceinline__ void bulk_g2s(uint32_t dst, const void* src, uint32_t bytes,
                                         uint32_t mbar) {
    asm volatile(
        "cp.async.bulk.shared::cluster.global.mbarrier::complete_tx::bytes [%0], [%1], %2, [%3];"
        :: "r"(dst), "l"(src), "r"(bytes), "r"(mbar) : "memory");
}
#define MBARRIER_INIT(mb, cnt) \
    asm volatile("mbarrier.init.shared.b64 [%0], %1;" :: "r"(mb), "r"((uint32_t)(cnt)) : "memory")
#define MBARRIER_EXPECT_TX(mb, bytes) \
    asm volatile("mbarrier.arrive.expect_tx.shared.b64 _, [%0], %1;" \
                 :: "r"(mb), "r"((uint32_t)(bytes)) : "memory")
#define MBARRIER_WAIT_PARITY(mb, ph) do { \
    uint32_t _mb = (mb); uint32_t _p = (uint32_t)(ph); uint32_t _done; \
    asm volatile("{\n\t.reg .pred p;\n\t" \
        "mbarrier.try_wait.parity.acquire.cta.shared::cta.b64 p, [%1], %2;\n\t" \
        "selp.b32 %0, 1, 0, p;\n\t}" : "=r"(_done) : "r"(_mb), "r"(_p) : "memory"); \
    if (!_done) { \
        asm volatile("{\n\t.reg .pred P1;\n\t" \
            "WL_%=:\n\t" \
            "mbarrier.try_wait.parity.acquire.cta.shared::cta.b64 P1, [%0], %1, 0x989680;\n\t" \
            "@P1 bra.uni WD_%=;\n\t" \
            "bra.uni WL_%=;\n\t" \
            "WD_%=:\n\t}" :: "r"(_mb), "r"(_p) : "memory"); \
    } \
} while (0)

__device__ __forceinline__ void ldsm4(uint32_t* r, uint32_t addr) {
    asm volatile("ldmatrix.sync.aligned.m8n8.x4.shared.b16 {%0,%1,%2,%3}, [%4];"
                 : "=r"(r[0]), "=r"(r[1]), "=r"(r[2]), "=r"(r[3]) : "r"(addr));
}
__device__ __forceinline__ void mma_fp8(float* c, const uint32_t* a, const uint32_t* b) {
    asm volatile(
        "mma.sync.aligned.m16n8k32.row.col.f32.e4m3.e4m3.f32 "
        "{%0,%1,%2,%3}, {%4,%5,%6,%7}, {%8,%9}, {%0,%1,%2,%3};"
        : "+f"(c[0]), "+f"(c[1]), "+f"(c[2]), "+f"(c[3])
        : "r"(a[0]), "r"(a[1]), "r"(a[2]), "r"(a[3]), "r"(b[0]), "r"(b[1]));
}
__device__ __forceinline__ uint32_t pack_e4m3x4(float v0, float v1, float v2, float v3) {
    uint16_t h0, h1;
    asm("cvt.rn.satfinite.e4m3x2.f32 %0, %1, %2;" : "=h"(h0) : "f"(v1), "f"(v0));
    asm("cvt.rn.satfinite.e4m3x2.f32 %0, %1, %2;" : "=h"(h1) : "f"(v3), "f"(v2));
    return (uint32_t)h0 | ((uint32_t)h1 << 16);
}

// ---------------- kernels ----------------
__global__ void init_kernel() { g_maxidx = 0; }

// one warp per row: fp32 norm + e4m3 convert, written in tile-major pre-swizzled order
__global__ void convert_kernel(const float* __restrict__ x, const float* __restrict__ emb) {
    int warp = (blockIdx.x * blockDim.x + threadIdx.x) >> 5;
    int lane = threadIdx.x & 31;
    const float* src; uint8_t* dst; float* nrm; int row; float sc;
    if (warp < N_ROWS) { src = x; dst = g_qx; nrm = g_xnorm; row = warp; sc = 1.0f; }
    else               { src = emb; dst = g_qe; nrm = g_enorm; row = warp - N_ROWS; sc = ESCALE; }
    const float4* p = reinterpret_cast<const float4*>(src + (size_t)row * DIM);
    const int rb = row >> 7, rl = row & 127;
    uint8_t* tbase0 = dst + ((size_t)rb * NSTAGES << 14);
    float s = 0.f;
    #pragma unroll
    for (int c = lane; c < DIM / 4; c += 32) {
        float4 v = p[c];
        s += v.x * v.x + v.y * v.y + v.z * v.z + v.w * v.w;
        uint32_t pk = pack_e4m3x4(v.x * sc, v.y * sc, v.z * sc, v.w * sc);
        int col4 = c * 4;                 // byte index within row (fp8 = 1B/elem)
        int kc = col4 >> 7;
        uint32_t byte = (uint32_t)(col4 & 127);
        uint32_t off = ((uint32_t)kc << 14)
                     + SWZ(((uint32_t)rl << 7) | (byte & 0x70u)) + (byte & 15u);
        *reinterpret_cast<uint32_t*>(tbase0 + off) = pk;
    }
    #pragma unroll
    for (int off = 16; off; off >>= 1) s += __shfl_xor_sync(0xffffffffu, s, off);
    if (lane == 0) nrm[row] = s;
}

// fast e4m3 HMMA GEMM, TMA-bulk fed: per CTA 128 rows x 128 codes x K=512.
// Epilogue: d~ = enorm - (2/8192)*dot, per-row min over 8-code chunks -> g_cmin.
__global__ void __launch_bounds__(256, 2) vq_gemm_kernel() {
    extern __shared__ __align__(1024) char smem[];
    const int tid = threadIdx.x;
    const int w = tid >> 5, l = tid & 31;
    const int cb = blockIdx.y * BN;
    const uint32_t sb = smem_u32(smem);
    const uint32_t mb = sb + SM_MBAR;
    float* senorm = reinterpret_cast<float*>(smem + SM_ENORM);

    if (tid == 0) {
        MBARRIER_INIT(mb + 0, 1);
        MBARRIER_INIT(mb + 8, 1);
        MBARRIER_INIT(mb + 16, 1);
    }
    if (tid < BN) senorm[tid] = g_enorm[cb + tid];
    __syncthreads();

    const uint8_t* aT = g_qx + ((size_t)blockIdx.x * NSTAGES << 14);
    const uint8_t* bT = g_qe + ((size_t)blockIdx.y * NSTAGES << 14);

    if (tid == 0) {
        #pragma unroll
        for (int s = 0; s < 3; s++) {
            uint32_t bar = mb + s * 8;
            uint32_t stg = sb + (uint32_t)s * STG_BYTES;
            MBARRIER_EXPECT_TX(bar, 2 * TILE_BYTES);
            bulk_g2s(stg,           aT + ((size_t)s << 14), TILE_BYTES, bar);
            bulk_g2s(stg + SM_BOFF, bT + ((size_t)s << 14), TILE_BYTES, bar);
        }
    }

    // warp layout: 2 (M) x 4 (N); warp tile 64 x 32
    const int m0 = (w >> 2) * 64;
    const int n0 = (w & 3) * 32;
    const int aRowLane = l & 15;
    const int aChunkHi = l >> 4;
    const int bRowLane = ((l >> 4) & 1) * 8 + (l & 7);
    const int bChunkHi = (l >> 3) & 1;

    float c[4][4][4];
    #pragma unroll
    for (int mt = 0; mt < 4; mt++)
        #pragma unroll
        for (int nt = 0; nt < 4; nt++)
            #pragma unroll
            for (int e = 0; e < 4; e++) c[mt][nt][e] = 0.f;

    for (int i = 0; i < NSTAGES; i++) {
        const int buf = i % 3;
        MBARRIER_WAIT_PARITY(mb + buf * 8, (i / 3) & 1);
        const uint32_t aStg = sb + (uint32_t)buf * STG_BYTES;
        const uint32_t bStg = aStg + SM_BOFF;
        #pragma unroll
        for (int ks = 0; ks < 4; ks++) {          // 4 x K32 per 128B stage
            uint32_t a[4][4], b[4][2];
            #pragma unroll
            for (int mt = 0; mt < 4; mt++) {
                uint32_t off = (uint32_t)((m0 + mt * 16 + aRowLane) * 128
                                          + (ks * 2 + aChunkHi) * 16);
                ldsm4(a[mt], aStg + SWZ(off));
            }
            #pragma unroll
            for (int nt2 = 0; nt2 < 2; nt2++) {
                uint32_t r4[4];
                uint32_t off = (uint32_t)((n0 + nt2 * 16 + bRowLane) * 128
                                          + (ks * 2 + bChunkHi) * 16);
                ldsm4(r4, bStg + SWZ(off));
                b[nt2 * 2][0] = r4[0]; b[nt2 * 2][1] = r4[1];
                b[nt2 * 2 + 1][0] = r4[2]; b[nt2 * 2 + 1][1] = r4[3];
            }
            #pragma unroll
            for (int mt = 0; mt < 4; mt++)
                #pragma unroll
                for (int nt = 0; nt < 4; nt++)
                    mma_fp8(c[mt][nt], a[mt], b[nt]);
        }
        __syncthreads();                          // all readers done with buf
        if (tid == 0 && i + 3 < NSTAGES) {
            uint32_t bar = mb + buf * 8;
            uint32_t stg = sb + (uint32_t)buf * STG_BYTES;
            MBARRIER_EXPECT_TX(bar, 2 * TILE_BYTES);
            bulk_g2s(stg,           aT + ((size_t)(i + 3) << 14), TILE_BYTES, bar);
            bulk_g2s(stg + SM_BOFF, bT + ((size_t)(i + 3) << 14), TILE_BYTES, bar);
        }
    }

    // ---- epilogue: chunk (8-code) mins -> smem staging -> coalesced gmem
    __syncthreads();
    float* sbuf = reinterpret_cast<float*>(smem);   // [128][20]

    const int j0 = (l & 3) * 2;
    #pragma unroll
    for (int mt = 0; mt < 4; mt++) {
        #pragma unroll
        for (int nt = 0; nt < 4; nt++) {
            const int colBase = n0 + nt * 8 + j0;
            float en0 = senorm[colBase], en1 = senorm[colBase + 1];
            float v0 = fminf(en0 - DSCALE * c[mt][nt][0], en1 - DSCALE * c[mt][nt][1]);
            float v1 = fminf(en0 - DSCALE * c[mt][nt][2], en1 - DSCALE * c[mt][nt][3]);
            #pragma unroll
            for (int off = 1; off <= 2; off <<= 1) {
                v0 = fminf(v0, __shfl_xor_sync(0xffffffffu, v0, off));
                v1 = fminf(v1, __shfl_xor_sync(0xffffffffu, v1, off));
            }
            if ((l & 3) == 0) {
                int rloc = m0 + mt * 16 + (l >> 2);
                int chLoc = (w & 3) * 4 + nt;
                sbuf[rloc * 20 + chLoc] = v0;
                sbuf[(rloc + 8) * 20 + chLoc] = v1;
            }
        }
    }
    __syncthreads();
    {
        int row = tid >> 1, half = tid & 1;
        const float* s = &sbuf[row * 20 + half * 8];
        float4 o0 = make_float4(s[0], s[1], s[2], s[3]);
        float4 o1 = make_float4(s[4], s[5], s[6], s[7]);
        float* dst = &g_cmin[(size_t)(blockIdx.x * BM + row) * NCH + blockIdx.y * 16 + half * 8];
        reinterpret_cast<float4*>(dst)[0] = o0;
        reinterpret_cast<float4*>(dst)[1] = o1;
    }
}

// block-per-row: scan chunk mins, exact-rescore candidate chunks (8 warps = 8 codes
// in parallel), then fused gather + straight-through + rowsq. grid N_ROWS, block 256.
__global__ void __launch_bounds__(256) argmin_kernel(const float* __restrict__ x,
                                                     const float* __restrict__ emb,
                                                     float* __restrict__ out) {
    __shared__ __align__(16) float sx[DIM];
    __shared__ float sred[8];
    __shared__ int   slist[256];
    __shared__ int   scount;
    __shared__ float sd[8];
    __shared__ int   sbesti;

    const int row = blockIdx.x;
    const int tid = threadIdx.x, w = tid >> 5, l = tid & 31;

    if (tid < 128)
        reinterpret_cast<float4*>(sx)[tid] =
            reinterpret_cast<const float4*>(x + (size_t)row * DIM)[tid];
    if (tid == 0) scount = 0;

    // scan 1024 chunk mins (one float4 per thread)
    float4 cv = reinterpret_cast<const float4*>(&g_cmin[(size_t)row * NCH])[tid];
    float lmin = fminf(fminf(cv.x, cv.y), fminf(cv.z, cv.w));
    #pragma unroll
    for (int off = 16; off; off >>= 1) lmin = fminf(lmin, __shfl_xor_sync(0xffffffffu, lmin, off));
    if (l == 0) sred[w] = lmin;
    __syncthreads();
    float thr = fminf(fminf(fminf(sred[0], sred[1]), fminf(sred[2], sred[3])),
                      fminf(fminf(sred[4], sred[5]), fminf(sred[6], sred[7]))) + EPS;
    #pragma unroll
    for (int e = 0; e < 4; e++) {
        if ((&cv.x)[e] <= thr) {
            int p = atomicAdd(&scount, 1);
            if (p < 256) slist[p] = tid * 4 + e;
        }
    }
    __syncthreads();
    const int count = min(scount, 256);

    const float xn = g_xnorm[row];
    float bestd = 3.4028235e38f;
    int besti = 0x7fffffff;

    for (int k = 0; k < count; k++) {
        const int ci = slist[k];
        const int code = ci * CH + w;
        const float4* e4 = reinterpret_cast<const float4*>(emb + (size_t)code * DIM);
        const float4* xs = reinterpret_cast<const float4*>(sx);
        float acc = 0.f;
        #pragma unroll
        for (int t = 0; t < 4; t++) {
            float4 ev = e4[l + 32 * t];
            float4 xv = xs[l + 32 * t];
            acc = fmaf(ev.x, xv.x, acc);
            acc = fmaf(ev.y, xv.y, acc);
            acc = fmaf(ev.z, xv.z, acc);
            acc = fmaf(ev.w, xv.w, acc);
        }
        #pragma unroll
        for (int off = 16; off; off >>= 1) acc += __shfl_xor_sync(0xffffffffu, acc, off);
        if (l == 0) sd[w] = __fsub_rn(__fadd_rn(xn, g_enorm[code]), 2.0f * acc);
        __syncthreads();
        if (tid == 0) {
            #pragma unroll
            for (int ww = 0; ww < 8; ww++) {
                float d = sd[ww];
                int id = ci * CH + ww;
                if (d < bestd || (d == bestd && id < besti)) { bestd = d; besti = id; }
            }
        }
        __syncthreads();
    }

    if (tid == 0) {
        sbesti = besti;
        out[Q_ELEMS + 2 + row] = (float)besti;
        atomicMax(&g_maxidx, besti);
    }
    __syncthreads();
    const int idx = sbesti;

    // fused gather + straight-through + rowsq (2 floats per thread)
    const float2* q2 = reinterpret_cast<const float2*>(emb + (size_t)idx * DIM);
    const float2* x2 = reinterpret_cast<const float2*>(sx);
    float2 qv = q2[tid], xv = x2[tid];
    float2 ov;
    float d0 = __fsub_rn(qv.x, xv.x); ov.x = __fadd_rn(xv.x, d0);
    float d1 = __fsub_rn(qv.y, xv.y); ov.y = __fadd_rn(xv.y, d1);
    reinterpret_cast<float2*>(out + (size_t)row * DIM)[tid] = ov;
    float ss = d0 * d0 + d1 * d1;
    #pragma unroll
    for (int off = 16; off; off >>= 1) ss += __shfl_xor_sync(0xffffffffu, ss, off);
    if (l == 0) sred[w] = ss;
    __syncthreads();
    if (tid == 0) {
        float t = 0.f;
        #pragma unroll
        for (int ww = 0; ww < 8; ww++) t += sred[ww];
        g_rowsq[row] = t;
    }
}

__global__ void scalars_kernel(float* __restrict__ out) {
    __shared__ float red[1024];
    const int tid = threadIdx.x;
    float s = 0.f;
    for (int r = tid; r < N_ROWS; r += 1024) s += g_rowsq[r];
    red[tid] = s;
    __syncthreads();
    #pragma unroll
    for (int st = 512; st > 0; st >>= 1) {
        if (tid < st) red[tid] += red[tid + st];
        __syncthreads();
    }
    if (tid == 0) {
        float mean = red[0] / (float)Q_ELEMS;
        out[Q_ELEMS] = 1.25f * mean;
        float L = (float)(g_maxidx + 1);
        float avg = 1.0f / L;
        out[Q_ELEMS + 1] = expf(-avg * logf(avg + 1e-10f));
    }
}

extern "C" void kernel_launch(void* const* d_in, const int* in_sizes, int n_in,
                              void* d_out, int out_size) {
    const float* x   = (const float*)d_in[0];
    const float* emb = (const float*)d_in[1];
    float* out = (float*)d_out;

    cudaFuncSetAttribute(vq_gemm_kernel, cudaFuncAttributeMaxDynamicSharedMemorySize, SM_TOTAL);

    init_kernel<<<1, 1>>>();
    convert_kernel<<<(N_ROWS + N_CODES) / 8, 256>>>(x, emb);
    vq_gemm_kernel<<<dim3(N_ROWS / BM, N_CODES / BN), 256, SM_TOTAL>>>();
    argmin_kernel<<<N_ROWS, 256>>>(x, emb, out);
    scalars_kernel<<<1, 1024>>>(out);
}

// round 7
// speedup vs baseline: 3.1124x; 1.5244x over previous
#include <cuda_runtime.h>
#include <cuda_bf16.h>
#include <cstdint>

// ---------------- problem constants ----------------
#define N_ROWS   16384
#define N_CODES  8192
#define DIM      512
#define Q_ELEMS  (N_ROWS * DIM)

// ---------------- GEMM tiling (bf16) ----------------
#define BM 128
#define BN 128
#define KC 64                 // K elems per stage = 128 B per row
#define NSTAGES (DIM / KC)    // 8
#define CH 8                  // codes per argmin chunk
#define NCH (N_CODES / CH)    // 1024 chunk-mins per row
#define EPS 5.0e-4f
#define MAXCAND 64            // max candidate chunks per row

// dynamic smem: 3 stages x (A 16KB + B 16KB) = 98304; enorm after
#define STG_BYTES 32768
#define SM_BOFF   16384
#define SM_ENORM  98304
#define SM_TOTAL  (98304 + 512)

// ---------------- scratch (device globals; no allocation allowed) ----------------
__device__ __align__(256) __nv_bfloat16 g_hx[(size_t)N_ROWS * DIM];
__device__ __align__(256) __nv_bfloat16 g_he[(size_t)N_CODES * DIM];
__device__ float g_xnorm[N_ROWS];
__device__ float g_enorm[N_CODES];
__device__ float g_cmin[(size_t)N_ROWS * NCH];
__device__ float g_rowsq[N_ROWS];
__device__ int   g_maxidx;

// ---------------- PTX helpers ----------------
__device__ __forceinline__ uint32_t smem_u32(const void* p) {
    uint32_t a;
    asm("{ .reg .u64 t; cvta.to.shared.u64 t, %1; cvt.u32.u64 %0, t; }"
        : "=r"(a) : "l"(p));
    return a;
}
__device__ __forceinline__ void cp16(uint32_t dst, const void* src) {
    asm volatile("cp.async.cg.shared.global [%0], [%1], 16;" :: "r"(dst), "l"(src) : "memory");
}
#define CP_COMMIT() asm volatile("cp.async.commit_group;" ::: "memory")
#define CP_WAIT(n)  asm volatile("cp.async.wait_group %0;" :: "n"(n) : "memory")

#define SWZ(b) ((b) ^ (((b) >> 3) & 0x70))

__device__ __forceinline__ void ldsm4(uint32_t* r, uint32_t addr) {
    asm volatile("ldmatrix.sync.aligned.m8n8.x4.shared.b16 {%0,%1,%2,%3}, [%4];"
                 : "=r"(r[0]), "=r"(r[1]), "=r"(r[2]), "=r"(r[3]) : "r"(addr));
}
__device__ __forceinline__ void mma16816(float* c, const uint32_t* a, const uint32_t* b) {
    asm volatile(
        "mma.sync.aligned.m16n8k16.row.col.f32.bf16.bf16.f32 "
        "{%0,%1,%2,%3}, {%4,%5,%6,%7}, {%8,%9}, {%0,%1,%2,%3};"
        : "+f"(c[0]), "+f"(c[1]), "+f"(c[2]), "+f"(c[3])
        : "r"(a[0]), "r"(a[1]), "r"(a[2]), "r"(a[3]), "r"(b[0]), "r"(b[1]));
}

// ---------------- kernels ----------------
__global__ void init_kernel() { g_maxidx = 0; }

// one warp per row: fp32 norm + bf16 convert
__global__ void convert_kernel(const float* __restrict__ x, const float* __restrict__ emb) {
    int warp = (blockIdx.x * blockDim.x + threadIdx.x) >> 5;
    int lane = threadIdx.x & 31;
    const float* src; __nv_bfloat16* dst; float* nrm; int row;
    if (warp < N_ROWS) { src = x; dst = g_hx; nrm = g_xnorm; row = warp; }
    else               { src = emb; dst = g_he; nrm = g_enorm; row = warp - N_ROWS; }
    const float4* p = reinterpret_cast<const float4*>(src + (size_t)row * DIM);
    uint2* o = reinterpret_cast<uint2*>(dst + (size_t)row * DIM);
    float s = 0.f;
    #pragma unroll
    for (int c = lane; c < DIM / 4; c += 32) {
        float4 v = p[c];
        s += v.x * v.x + v.y * v.y + v.z * v.z + v.w * v.w;
        __nv_bfloat162 lo = __floats2bfloat162_rn(v.x, v.y);
        __nv_bfloat162 hi = __floats2bfloat162_rn(v.z, v.w);
        uint2 u;
        u.x = *reinterpret_cast<unsigned*>(&lo);
        u.y = *reinterpret_cast<unsigned*>(&hi);
        o[c] = u;
    }
    #pragma unroll
    for (int off = 16; off; off >>= 1) s += __shfl_xor_sync(0xffffffffu, s, off);
    if (lane == 0) nrm[row] = s;
}

// bf16 HMMA GEMM: 128x128xK512 per CTA, 256 thr, 3-stage cp.async, ONE sync/stage.
// Epilogue: d~ = enorm - 2*dot, per-row min over 8-code chunks -> g_cmin.
__global__ void __launch_bounds__(256, 2) vq_gemm_kernel() {
    extern __shared__ __align__(1024) char smem[];
    const int tid = threadIdx.x;
    const int w = tid >> 5, l = tid & 31;
    const int rowBase = blockIdx.x * BM;
    const int cb = blockIdx.y * BN;
    const uint32_t sb = smem_u32(smem);
    float* senorm = reinterpret_cast<float*>(smem + SM_ENORM);

    if (tid < BN) senorm[tid] = g_enorm[cb + tid];

    // warp layout: 2 (M) x 4 (N); warp tile 64 x 32
    const int m0 = (w >> 2) * 64;
    const int n0 = (w & 3) * 32;
    const int aRowLane = l & 15;
    const int aChunkHi = l >> 4;
    const int bRowLane = ((l >> 4) & 1) * 8 + (l & 7);
    const int bChunkHi = (l >> 3) & 1;

    float c[4][4][4];
    #pragma unroll
    for (int mt = 0; mt < 4; mt++)
        #pragma unroll
        for (int nt = 0; nt < 4; nt++)
            #pragma unroll
            for (int e = 0; e < 4; e++) c[mt][nt][e] = 0.f;

    auto load_stage = [&](int kc, int s) {
        const int kb = kc * KC;
        const uint32_t stg = sb + (uint32_t)s * STG_BYTES;
        #pragma unroll
        for (int q = 0; q < 4; q++) {
            int t = tid + q * 256;
            int r = t >> 3, ch = t & 7;
            cp16(stg + SWZ((uint32_t)(r * 128 + ch * 16)),
                 g_hx + (size_t)(rowBase + r) * DIM + kb + ch * 8);
        }
        #pragma unroll
        for (int q = 0; q < 4; q++) {
            int t = tid + q * 256;
            int r = t >> 3, ch = t & 7;
            cp16(stg + SM_BOFF + SWZ((uint32_t)(r * 128 + ch * 16)),
                 g_he + (size_t)(cb + r) * DIM + kb + ch * 8);
        }
        CP_COMMIT();
    };

    load_stage(0, 0);
    load_stage(1, 1);

    #pragma unroll
    for (int i = 0; i < NSTAGES; i++) {
        if (i < NSTAGES - 1) CP_WAIT(1); else CP_WAIT(0);
        __syncthreads();                  // stage i ready; all warps done with i-1
        if (i + 2 < NSTAGES) load_stage(i + 2, (i + 2) % 3);   // overwrite buf of i-1
        const uint32_t aStg = sb + (uint32_t)(i % 3) * STG_BYTES;
        const uint32_t bStg = aStg + SM_BOFF;
        #pragma unroll
        for (int ks = 0; ks < 4; ks++) {
            uint32_t a[4][4], b[4][2];
            #pragma unroll
            for (int mt = 0; mt < 4; mt++) {
                uint32_t off = (uint32_t)((m0 + mt * 16 + aRowLane) * 128
                                          + (ks * 2 + aChunkHi) * 16);
                ldsm4(a[mt], aStg + SWZ(off));
            }
            #pragma unroll
            for (int nt2 = 0; nt2 < 2; nt2++) {
                uint32_t r4[4];
                uint32_t off = (uint32_t)((n0 + nt2 * 16 + bRowLane) * 128
                                          + (ks * 2 + bChunkHi) * 16);
                ldsm4(r4, bStg + SWZ(off));
                b[nt2 * 2][0] = r4[0]; b[nt2 * 2][1] = r4[1];
                b[nt2 * 2 + 1][0] = r4[2]; b[nt2 * 2 + 1][1] = r4[3];
            }
            #pragma unroll
            for (int mt = 0; mt < 4; mt++)
                #pragma unroll
                for (int nt = 0; nt < 4; nt++)
                    mma16816(c[mt][nt], a[mt], b[nt]);
        }
    }

    // ---- epilogue: chunk (8-code) mins -> smem staging -> coalesced gmem
    __syncthreads();
    float* sbuf = reinterpret_cast<float*>(smem);   // [128][20]

    const int j0 = (l & 3) * 2;
    #pragma unroll
    for (int mt = 0; mt < 4; mt++) {
        #pragma unroll
        for (int nt = 0; nt < 4; nt++) {
            const int colBase = n0 + nt * 8 + j0;
            float en0 = senorm[colBase], en1 = senorm[colBase + 1];
            float v0 = fminf(en0 - 2.0f * c[mt][nt][0], en1 - 2.0f * c[mt][nt][1]);
            float v1 = fminf(en0 - 2.0f * c[mt][nt][2], en1 - 2.0f * c[mt][nt][3]);
            #pragma unroll
            for (int off = 1; off <= 2; off <<= 1) {
                v0 = fminf(v0, __shfl_xor_sync(0xffffffffu, v0, off));
                v1 = fminf(v1, __shfl_xor_sync(0xffffffffu, v1, off));
            }
            if ((l & 3) == 0) {
                int rloc = m0 + mt * 16 + (l >> 2);
                int chLoc = (w & 3) * 4 + nt;
                sbuf[rloc * 20 + chLoc] = v0;
                sbuf[(rloc + 8) * 20 + chLoc] = v1;
            }
        }
    }
    __syncthreads();
    {
        int row = tid >> 1, half = tid & 1;
        const float* s = &sbuf[row * 20 + half * 8];
        float4 o0 = make_float4(s[0], s[1], s[2], s[3]);
        float4 o1 = make_float4(s[4], s[5], s[6], s[7]);
        float* dst = &g_cmin[(size_t)(blockIdx.x * BM + row) * NCH + blockIdx.y * 16 + half * 8];
        reinterpret_cast<float4*>(dst)[0] = o0;
        reinterpret_cast<float4*>(dst)[1] = o1;
    }
}

// block-per-row exact argmin + fused gather. Candidate codes scored flat-parallel
// across 8 warps (no syncs in the loop); packed u64 keys give exact tie-break.
__global__ void __launch_bounds__(256) argmin_kernel(const float* __restrict__ x,
                                                     const float* __restrict__ emb,
                                                     float* __restrict__ out) {
    __shared__ __align__(16) float sx[DIM];
    __shared__ float sred[8];
    __shared__ int   slist[MAXCAND];
    __shared__ int   scount;
    __shared__ unsigned long long skey[MAXCAND * CH];
    __shared__ int   sbesti;

    const int row = blockIdx.x;
    const int tid = threadIdx.x, w = tid >> 5, l = tid & 31;

    if (tid < 128)
        reinterpret_cast<float4*>(sx)[tid] =
            reinterpret_cast<const float4*>(x + (size_t)row * DIM)[tid];
    if (tid == 0) scount = 0;

    // scan 1024 chunk mins (one float4 per thread)
    float4 cv = reinterpret_cast<const float4*>(&g_cmin[(size_t)row * NCH])[tid];
    float lmin = fminf(fminf(cv.x, cv.y), fminf(cv.z, cv.w));
    #pragma unroll
    for (int off = 16; off; off >>= 1) lmin = fminf(lmin, __shfl_xor_sync(0xffffffffu, lmin, off));
    if (l == 0) sred[w] = lmin;
    __syncthreads();
    float thr = fminf(fminf(fminf(sred[0], sred[1]), fminf(sred[2], sred[3])),
                      fminf(fminf(sred[4], sred[5]), fminf(sred[6], sred[7]))) + EPS;
    #pragma unroll
    for (int e = 0; e < 4; e++) {
        if ((&cv.x)[e] <= thr) {
            int p = atomicAdd(&scount, 1);
            if (p < MAXCAND) slist[p] = tid * 4 + e;
        }
    }
    __syncthreads();
    const int count = min(scount, MAXCAND);
    const int ncodes = count * CH;
    const float xn = g_xnorm[row];

    // flat-parallel exact rescore: warp w handles codes w, w+8, w+16, ...
    for (int k = w; k < ncodes; k += 8) {
        const int code = slist[k >> 3] * CH + (k & 7);
        const float4* e4 = reinterpret_cast<const float4*>(emb + (size_t)code * DIM);
        const float4* xs = reinterpret_cast<const float4*>(sx);
        float acc = 0.f;
        #pragma unroll
        for (int t = 0; t < 4; t++) {
            float4 ev = e4[l + 32 * t];
            float4 xv = xs[l + 32 * t];
            acc = fmaf(ev.x, xv.x, acc);
            acc = fmaf(ev.y, xv.y, acc);
            acc = fmaf(ev.z, xv.z, acc);
            acc = fmaf(ev.w, xv.w, acc);
        }
        #pragma unroll
        for (int off = 16; off; off >>= 1) acc += __shfl_xor_sync(0xffffffffu, acc, off);
        if (l == 0) {
            float d = __fsub_rn(__fadd_rn(xn, g_enorm[code]), 2.0f * acc);
            // d > 0 always (distances ~512): float bits are order-preserving
            skey[k] = ((unsigned long long)__float_as_uint(d) << 32) | (unsigned)code;
        }
    }
    __syncthreads();

    // final min over packed keys (warp 0)
    if (w == 0) {
        unsigned long long best = 0xffffffffffffffffull;
        for (int k = l; k < ncodes; k += 32) best = min(best, skey[k]);
        #pragma unroll
        for (int off = 16; off; off >>= 1) {
            unsigned long long o = __shfl_xor_sync(0xffffffffu, best, off);
            best = min(best, o);
        }
        if (l == 0) {
            int bi = (int)(best & 0xffffffffu);
            sbesti = bi;
            out[Q_ELEMS + 2 + row] = (float)bi;
            atomicMax(&g_maxidx, bi);
        }
    }
    __syncthreads();
    const int idx = sbesti;

    // fused gather + straight-through + rowsq (2 floats per thread)
    const float2* q2 = reinterpret_cast<const float2*>(emb + (size_t)idx * DIM);
    const float2* x2 = reinterpret_cast<const float2*>(sx);
    float2 qv = q2[tid], xv = x2[tid];
    float2 ov;
    float d0 = __fsub_rn(qv.x, xv.x); ov.x = __fadd_rn(xv.x, d0);
    float d1 = __fsub_rn(qv.y, xv.y); ov.y = __fadd_rn(xv.y, d1);
    reinterpret_cast<float2*>(out + (size_t)row * DIM)[tid] = ov;
    float ss = d0 * d0 + d1 * d1;
    #pragma unroll
    for (int off = 16; off; off >>= 1) ss += __shfl_xor_sync(0xffffffffu, ss, off);
    if (l == 0) sred[w] = ss;
    __syncthreads();
    if (tid == 0) {
        float t = 0.f;
        #pragma unroll
        for (int ww = 0; ww < 8; ww++) t += sred[ww];
        g_rowsq[row] = t;
    }
}

__global__ void scalars_kernel(float* __restrict__ out) {
    __shared__ float red[1024];
    const int tid = threadIdx.x;
    float s = 0.f;
    for (int r = tid; r < N_ROWS; r += 1024) s += g_rowsq[r];
    red[tid] = s;
    __syncthreads();
    #pragma unroll
    for (int st = 512; st > 0; st >>= 1) {
        if (tid < st) red[tid] += red[tid + st];
        __syncthreads();
    }
    if (tid == 0) {
        float mean = red[0] / (float)Q_ELEMS;
        out[Q_ELEMS] = 1.25f * mean;
        float L = (float)(g_maxidx + 1);
        float avg = 1.0f / L;
        out[Q_ELEMS + 1] = expf(-avg * logf(avg + 1e-10f));
    }
}

extern "C" void kernel_launch(void* const* d_in, const int* in_sizes, int n_in,
                              void* d_out, int out_size) {
    const float* x   = (const float*)d_in[0];
    const float* emb = (const float*)d_in[1];
    float* out = (float*)d_out;

    cudaFuncSetAttribute(vq_gemm_kernel, cudaFuncAttributeMaxDynamicSharedMemorySize, SM_TOTAL);

    init_kernel<<<1, 1>>>();
    convert_kernel<<<(N_ROWS + N_CODES) / 8, 256>>>(x, emb);
    vq_gemm_kernel<<<dim3(N_ROWS / BM, N_CODES / BN), 256, SM_TOTAL>>>();
    argmin_kernel<<<N_ROWS, 256>>>(x, emb, out);
    scalars_kernel<<<1, 1024>>>(out);
}

// round 8
// speedup vs baseline: 3.1834x; 1.0228x over previous
#include <cuda_runtime.h>
#include <cuda_bf16.h>
#include <cstdint>

// ---------------- problem constants ----------------
#define N_ROWS   16384
#define N_CODES  8192
#define DIM      512
#define Q_ELEMS  (N_ROWS * DIM)

// ---------------- GEMM tiling (bf16) ----------------
#define BM 128
#define BN 128
#define KC 64                 // K elems per stage = 128 B per row
#define NSTAGES (DIM / KC)    // 8
#define CH 8                  // codes per argmin chunk
#define NCH (N_CODES / CH)    // 1024 chunk-mins per row
#define EPS 5.0e-4f
#define MAXCAND 64            // max candidate chunks per row

// dynamic smem: 3 stages x (A 16KB + B 16KB) = 98304; enorm after
#define STG_BYTES 32768
#define SM_BOFF   16384
#define SM_ENORM  98304
#define SM_TOTAL  (98304 + 512)

// ---------------- scratch (device globals; no allocation allowed) ----------------
__device__ __align__(256) __nv_bfloat16 g_hx[(size_t)N_ROWS * DIM];
__device__ __align__(256) __nv_bfloat16 g_he[(size_t)N_CODES * DIM];
__device__ float g_xnorm[N_ROWS];
__device__ float g_enorm[N_CODES];
__device__ float g_cmin[(size_t)N_ROWS * NCH];
__device__ float g_rowsq[N_ROWS];
__device__ int   g_cand[(size_t)N_ROWS * MAXCAND];
__device__ int   g_ccount[N_ROWS];
__device__ int   g_maxidx;

// ---------------- PTX helpers ----------------
__device__ __forceinline__ uint32_t smem_u32(const void* p) {
    uint32_t a;
    asm("{ .reg .u64 t; cvta.to.shared.u64 t, %1; cvt.u32.u64 %0, t; }"
        : "=r"(a) : "l"(p));
    return a;
}
__device__ __forceinline__ void cp16(uint32_t dst, const void* src) {
    asm volatile("cp.async.cg.shared.global [%0], [%1], 16;" :: "r"(dst), "l"(src) : "memory");
}
#define CP_COMMIT() asm volatile("cp.async.commit_group;" ::: "memory")
#define CP_WAIT(n)  asm volatile("cp.async.wait_group %0;" :: "n"(n) : "memory")

#define SWZ(b) ((b) ^ (((b) >> 3) & 0x70))

__device__ __forceinline__ void ldsm4(uint32_t* r, uint32_t addr) {
    asm volatile("ldmatrix.sync.aligned.m8n8.x4.shared.b16 {%0,%1,%2,%3}, [%4];"
                 : "=r"(r[0]), "=r"(r[1]), "=r"(r[2]), "=r"(r[3]) : "r"(addr));
}
__device__ __forceinline__ void mma16816(float* c, const uint32_t* a, const uint32_t* b) {
    asm volatile(
        "mma.sync.aligned.m16n8k16.row.col.f32.bf16.bf16.f32 "
        "{%0,%1,%2,%3}, {%4,%5,%6,%7}, {%8,%9}, {%0,%1,%2,%3};"
        : "+f"(c[0]), "+f"(c[1]), "+f"(c[2]), "+f"(c[3])
        : "r"(a[0]), "r"(a[1]), "r"(a[2]), "r"(a[3]), "r"(b[0]), "r"(b[1]));
}

// ---------------- kernels ----------------
__global__ void init_kernel() { g_maxidx = 0; }

// one warp per row: fp32 norm + bf16 convert
__global__ void convert_kernel(const float* __restrict__ x, const float* __restrict__ emb) {
    int warp = (blockIdx.x * blockDim.x + threadIdx.x) >> 5;
    int lane = threadIdx.x & 31;
    const float* src; __nv_bfloat16* dst; float* nrm; int row;
    if (warp < N_ROWS) { src = x; dst = g_hx; nrm = g_xnorm; row = warp; }
    else               { src = emb; dst = g_he; nrm = g_enorm; row = warp - N_ROWS; }
    const float4* p = reinterpret_cast<const float4*>(src + (size_t)row * DIM);
    uint2* o = reinterpret_cast<uint2*>(dst + (size_t)row * DIM);
    float s = 0.f;
    #pragma unroll
    for (int c = lane; c < DIM / 4; c += 32) {
        float4 v = p[c];
        s += v.x * v.x + v.y * v.y + v.z * v.z + v.w * v.w;
        __nv_bfloat162 lo = __floats2bfloat162_rn(v.x, v.y);
        __nv_bfloat162 hi = __floats2bfloat162_rn(v.z, v.w);
        uint2 u;
        u.x = *reinterpret_cast<unsigned*>(&lo);
        u.y = *reinterpret_cast<unsigned*>(&hi);
        o[c] = u;
    }
    #pragma unroll
    for (int off = 16; off; off >>= 1) s += __shfl_xor_sync(0xffffffffu, s, off);
    if (lane == 0) nrm[row] = s;
}

// bf16 HMMA GEMM: 128x128xK512 per CTA, 256 thr, 3-stage cp.async, ONE sync/stage.
// Epilogue: d~ = enorm - 2*dot, per-row min over 8-code chunks -> g_cmin.
__global__ void __launch_bounds__(256, 2) vq_gemm_kernel() {
    extern __shared__ __align__(1024) char smem[];
    const int tid = threadIdx.x;
    const int w = tid >> 5, l = tid & 31;
    const int rowBase = blockIdx.x * BM;
    const int cb = blockIdx.y * BN;
    const uint32_t sb = smem_u32(smem);
    float* senorm = reinterpret_cast<float*>(smem + SM_ENORM);

    if (tid < BN) senorm[tid] = g_enorm[cb + tid];

    // warp layout: 2 (M) x 4 (N); warp tile 64 x 32
    const int m0 = (w >> 2) * 64;
    const int n0 = (w & 3) * 32;
    const int aRowLane = l & 15;
    const int aChunkHi = l >> 4;
    const int bRowLane = ((l >> 4) & 1) * 8 + (l & 7);
    const int bChunkHi = (l >> 3) & 1;

    float c[4][4][4];
    #pragma unroll
    for (int mt = 0; mt < 4; mt++)
        #pragma unroll
        for (int nt = 0; nt < 4; nt++)
            #pragma unroll
            for (int e = 0; e < 4; e++) c[mt][nt][e] = 0.f;

    auto load_stage = [&](int kc, int s) {
        const int kb = kc * KC;
        const uint32_t stg = sb + (uint32_t)s * STG_BYTES;
        #pragma unroll
        for (int q = 0; q < 4; q++) {
            int t = tid + q * 256;
            int r = t >> 3, ch = t & 7;
            cp16(stg + SWZ((uint32_t)(r * 128 + ch * 16)),
                 g_hx + (size_t)(rowBase + r) * DIM + kb + ch * 8);
        }
        #pragma unroll
        for (int q = 0; q < 4; q++) {
            int t = tid + q * 256;
            int r = t >> 3, ch = t & 7;
            cp16(stg + SM_BOFF + SWZ((uint32_t)(r * 128 + ch * 16)),
                 g_he + (size_t)(cb + r) * DIM + kb + ch * 8);
        }
        CP_COMMIT();
    };

    load_stage(0, 0);
    load_stage(1, 1);

    #pragma unroll
    for (int i = 0; i < NSTAGES; i++) {
        if (i < NSTAGES - 1) CP_WAIT(1); else CP_WAIT(0);
        __syncthreads();
        if (i + 2 < NSTAGES) load_stage(i + 2, (i + 2) % 3);
        const uint32_t aStg = sb + (uint32_t)(i % 3) * STG_BYTES;
        const uint32_t bStg = aStg + SM_BOFF;
        #pragma unroll
        for (int ks = 0; ks < 4; ks++) {
            uint32_t a[4][4], b[4][2];
            #pragma unroll
            for (int mt = 0; mt < 4; mt++) {
                uint32_t off = (uint32_t)((m0 + mt * 16 + aRowLane) * 128
                                          + (ks * 2 + aChunkHi) * 16);
                ldsm4(a[mt], aStg + SWZ(off));
            }
            #pragma unroll
            for (int nt2 = 0; nt2 < 2; nt2++) {
                uint32_t r4[4];
                uint32_t off = (uint32_t)((n0 + nt2 * 16 + bRowLane) * 128
                                          + (ks * 2 + bChunkHi) * 16);
                ldsm4(r4, bStg + SWZ(off));
                b[nt2 * 2][0] = r4[0]; b[nt2 * 2][1] = r4[1];
                b[nt2 * 2 + 1][0] = r4[2]; b[nt2 * 2 + 1][1] = r4[3];
            }
            #pragma unroll
            for (int mt = 0; mt < 4; mt++)
                #pragma unroll
                for (int nt = 0; nt < 4; nt++)
                    mma16816(c[mt][nt], a[mt], b[nt]);
        }
    }

    // ---- epilogue: chunk (8-code) mins -> smem staging -> coalesced gmem
    __syncthreads();
    float* sbuf = reinterpret_cast<float*>(smem);   // [128][20]

    const int j0 = (l & 3) * 2;
    #pragma unroll
    for (int mt = 0; mt < 4; mt++) {
        #pragma unroll
        for (int nt = 0; nt < 4; nt++) {
            const int colBase = n0 + nt * 8 + j0;
            float en0 = senorm[colBase], en1 = senorm[colBase + 1];
            float v0 = fminf(en0 - 2.0f * c[mt][nt][0], en1 - 2.0f * c[mt][nt][1]);
            float v1 = fminf(en0 - 2.0f * c[mt][nt][2], en1 - 2.0f * c[mt][nt][3]);
            #pragma unroll
            for (int off = 1; off <= 2; off <<= 1) {
                v0 = fminf(v0, __shfl_xor_sync(0xffffffffu, v0, off));
                v1 = fminf(v1, __shfl_xor_sync(0xffffffffu, v1, off));
            }
            if ((l & 3) == 0) {
                int rloc = m0 + mt * 16 + (l >> 2);
                int chLoc = (w & 3) * 4 + nt;
                sbuf[rloc * 20 + chLoc] = v0;
                sbuf[(rloc + 8) * 20 + chLoc] = v1;
            }
        }
    }
    __syncthreads();
    {
        int row = tid >> 1, half = tid & 1;
        const float* s = &sbuf[row * 20 + half * 8];
        float4 o0 = make_float4(s[0], s[1], s[2], s[3]);
        float4 o1 = make_float4(s[4], s[5], s[6], s[7]);
        float* dst = &g_cmin[(size_t)(blockIdx.x * BM + row) * NCH + blockIdx.y * 16 + half * 8];
        reinterpret_cast<float4*>(dst)[0] = o0;
        reinterpret_cast<float4*>(dst)[1] = o1;
    }
}

// warp-per-row streaming scan over g_cmin: min -> threshold -> compact candidate
// chunk ids to g_cand/g_ccount. grid N_ROWS/8, block 256. No smem, no block syncs.
__global__ void __launch_bounds__(256) scan_kernel() {
    const int lane = threadIdx.x & 31;
    const int row = blockIdx.x * 8 + (threadIdx.x >> 5);

    const float4* cm4 = reinterpret_cast<const float4*>(&g_cmin[(size_t)row * NCH]);
    float4 v[8];
    float lmin = 3.4028235e38f;
    #pragma unroll
    for (int q = 0; q < 8; q++) {
        v[q] = cm4[q * 32 + lane];
        lmin = fminf(fminf(fminf(lmin, v[q].x), fminf(v[q].y, v[q].z)), v[q].w);
    }
    #pragma unroll
    for (int off = 16; off; off >>= 1) lmin = fminf(lmin, __shfl_xor_sync(0xffffffffu, lmin, off));
    const float thr = lmin + EPS;

    int cnt = 0;
    int* cand = &g_cand[(size_t)row * MAXCAND];
    #pragma unroll
    for (int q = 0; q < 8; q++) {
        #pragma unroll
        for (int e = 0; e < 4; e++) {
            float ve = (&v[q].x)[e];
            unsigned m = __ballot_sync(0xffffffffu, ve <= thr);
            if (m) {
                if (ve <= thr) {
                    int rank = __popc(m & ((1u << lane) - 1));
                    int p = cnt + rank;
                    if (p < MAXCAND) cand[p] = q * 128 + lane * 4 + e;
                }
                cnt += __popc(m);
            }
        }
    }
    if (lane == 0) g_ccount[row] = min(cnt, MAXCAND);
}

// block-per-row exact rescore of candidate codes (flat-parallel across 8 warps,
// packed u64 keys for exact first-index tie-break) + fused gather/ST/rowsq.
__global__ void __launch_bounds__(256) rescore_kernel(const float* __restrict__ x,
                                                      const float* __restrict__ emb,
                                                      float* __restrict__ out) {
    __shared__ __align__(16) float sx[DIM];
    __shared__ float sred[8];
    __shared__ int   slist[MAXCAND];
    __shared__ unsigned long long skey[MAXCAND * CH];
    __shared__ int   sbesti;

    const int row = blockIdx.x;
    const int tid = threadIdx.x, w = tid >> 5, l = tid & 31;

    if (tid < 128)
        reinterpret_cast<float4*>(sx)[tid] =
            reinterpret_cast<const float4*>(x + (size_t)row * DIM)[tid];
    const int count = g_ccount[row];
    if (tid < count) slist[tid] = g_cand[(size_t)row * MAXCAND + tid];
    __syncthreads();

    const int ncodes = count * CH;
    const float xn = g_xnorm[row];

    for (int k = w; k < ncodes; k += 8) {
        const int code = slist[k >> 3] * CH + (k & 7);
        const float4* e4 = reinterpret_cast<const float4*>(emb + (size_t)code * DIM);
        const float4* xs = reinterpret_cast<const float4*>(sx);
        float acc = 0.f;
        #pragma unroll
        for (int t = 0; t < 4; t++) {
            float4 ev = e4[l + 32 * t];
            float4 xv = xs[l + 32 * t];
            acc = fmaf(ev.x, xv.x, acc);
            acc = fmaf(ev.y, xv.y, acc);
            acc = fmaf(ev.z, xv.z, acc);
            acc = fmaf(ev.w, xv.w, acc);
        }
        #pragma unroll
        for (int off = 16; off; off >>= 1) acc += __shfl_xor_sync(0xffffffffu, acc, off);
        if (l == 0) {
            float d = __fsub_rn(__fadd_rn(xn, g_enorm[code]), 2.0f * acc);
            skey[k] = ((unsigned long long)__float_as_uint(d) << 32) | (unsigned)code;
        }
    }
    __syncthreads();

    if (w == 0) {
        unsigned long long best = 0xffffffffffffffffull;
        for (int k = l; k < ncodes; k += 32) best = min(best, skey[k]);
        #pragma unroll
        for (int off = 16; off; off >>= 1) {
            unsigned long long o = __shfl_xor_sync(0xffffffffu, best, off);
            best = min(best, o);
        }
        if (l == 0) {
            int bi = (int)(best & 0xffffffffu);
            sbesti = bi;
            out[Q_ELEMS + 2 + row] = (float)bi;
            atomicMax(&g_maxidx, bi);
        }
    }
    __syncthreads();
    const int idx = sbesti;

    const float2* q2 = reinterpret_cast<const float2*>(emb + (size_t)idx * DIM);
    const float2* x2 = reinterpret_cast<const float2*>(sx);
    float2 qv = q2[tid], xv = x2[tid];
    float2 ov;
    float d0 = __fsub_rn(qv.x, xv.x); ov.x = __fadd_rn(xv.x, d0);
    float d1 = __fsub_rn(qv.y, xv.y); ov.y = __fadd_rn(xv.y, d1);
    reinterpret_cast<float2*>(out + (size_t)row * DIM)[tid] = ov;
    float ss = d0 * d0 + d1 * d1;
    #pragma unroll
    for (int off = 16; off; off >>= 1) ss += __shfl_xor_sync(0xffffffffu, ss, off);
    if (l == 0) sred[w] = ss;
    __syncthreads();
    if (tid == 0) {
        float t = 0.f;
        #pragma unroll
        for (int ww = 0; ww < 8; ww++) t += sred[ww];
        g_rowsq[row] = t;
    }
}

__global__ void scalars_kernel(float* __restrict__ out) {
    __shared__ float red[1024];
    const int tid = threadIdx.x;
    float s = 0.f;
    for (int r = tid; r < N_ROWS; r += 1024) s += g_rowsq[r];
    red[tid] = s;
    __syncthreads();
    #pragma unroll
    for (int st = 512; st > 0; st >>= 1) {
        if (tid < st) red[tid] += red[tid + st];
        __syncthreads();
    }
    if (tid == 0) {
        float mean = red[0] / (float)Q_ELEMS;
        out[Q_ELEMS] = 1.25f * mean;
        float L = (float)(g_maxidx + 1);
        float avg = 1.0f / L;
        out[Q_ELEMS + 1] = expf(-avg * logf(avg + 1e-10f));
    }
}

extern "C" void kernel_launch(void* const* d_in, const int* in_sizes, int n_in,
                              void* d_out, int out_size) {
    const float* x   = (const float*)d_in[0];
    const float* emb = (const float*)d_in[1];
    float* out = (float*)d_out;

    cudaFuncSetAttribute(vq_gemm_kernel, cudaFuncAttributeMaxDynamicSharedMemorySize, SM_TOTAL);

    init_kernel<<<1, 1>>>();
    convert_kernel<<<(N_ROWS + N_CODES) / 8, 256>>>(x, emb);
    vq_gemm_kernel<<<dim3(N_ROWS / BM, N_CODES / BN), 256, SM_TOTAL>>>();
    scan_kernel<<<N_ROWS / 8, 256>>>();
    rescore_kernel<<<N_ROWS, 256>>>(x, emb, out);
    scalars_kernel<<<1, 1024>>>(out);
}

// round 9
// speedup vs baseline: 3.4232x; 1.0754x over previous
#include <cuda_runtime.h>
#include <cuda_fp16.h>
#include <cstdint>

// ---------------- problem constants ----------------
#define N_ROWS   16384
#define N_CODES  8192
#define DIM      512
#define Q_ELEMS  (N_ROWS * DIM)

// ---------------- GEMM tiling (fp16 in, fp16 accum) ----------------
#define BM 128
#define BN 128
#define KC 64                 // K elems per stage = 128 B per row
#define NSTAGES (DIM / KC)    // 8
#define CH 8                  // codes per argmin chunk
#define NCH (N_CODES / CH)    // 1024 chunk-mins per row
#define EPS 4.0e-4f
#define MAXCAND 64            // max candidate chunks per row

// dynamic smem: 3 stages x (A 16KB + B 16KB) = 98304; enorm after
#define STG_BYTES 32768
#define SM_BOFF   16384
#define SM_ENORM  98304
#define SM_TOTAL  (98304 + 512)

// ---------------- scratch (device globals; no allocation allowed) ----------------
__device__ __align__(256) __half g_hx[(size_t)N_ROWS * DIM];
__device__ __align__(256) __half g_he[(size_t)N_CODES * DIM];
__device__ float  g_xnorm[N_ROWS];
__device__ float  g_enorm[N_CODES];
__device__ __align__(16) __half g_cmin[(size_t)N_ROWS * NCH];   // d~ chunk mins, fp16
__device__ float  g_rowsq[N_ROWS];
__device__ int    g_cand[(size_t)N_ROWS * MAXCAND];
__device__ int    g_ccount[N_ROWS];
__device__ int    g_maxidx;

// ---------------- PTX helpers ----------------
__device__ __forceinline__ uint32_t smem_u32(const void* p) {
    uint32_t a;
    asm("{ .reg .u64 t; cvta.to.shared.u64 t, %1; cvt.u32.u64 %0, t; }"
        : "=r"(a) : "l"(p));
    return a;
}
__device__ __forceinline__ void cp16(uint32_t dst, const void* src) {
    asm volatile("cp.async.cg.shared.global [%0], [%1], 16;" :: "r"(dst), "l"(src) : "memory");
}
#define CP_COMMIT() asm volatile("cp.async.commit_group;" ::: "memory")
#define CP_WAIT(n)  asm volatile("cp.async.wait_group %0;" :: "n"(n) : "memory")

#define SWZ(b) ((b) ^ (((b) >> 3) & 0x70))

__device__ __forceinline__ void ldsm4(uint32_t* r, uint32_t addr) {
    asm volatile("ldmatrix.sync.aligned.m8n8.x4.shared.b16 {%0,%1,%2,%3}, [%4];"
                 : "=r"(r[0]), "=r"(r[1]), "=r"(r[2]), "=r"(r[3]) : "r"(addr));
}
// fp16 in, fp16 accum: C/D are 2 b32 regs (4 halves)
__device__ __forceinline__ void mma16816_h(uint32_t* c, const uint32_t* a, const uint32_t* b) {
    asm volatile(
        "mma.sync.aligned.m16n8k16.row.col.f16.f16.f16.f16 "
        "{%0,%1}, {%2,%3,%4,%5}, {%6,%7}, {%0,%1};"
        : "+r"(c[0]), "+r"(c[1])
        : "r"(a[0]), "r"(a[1]), "r"(a[2]), "r"(a[3]), "r"(b[0]), "r"(b[1]));
}

// ---------------- kernels ----------------
__global__ void init_kernel() { g_maxidx = 0; }

// one warp per row: fp32 norm + fp16 convert
__global__ void convert_kernel(const float* __restrict__ x, const float* __restrict__ emb) {
    int warp = (blockIdx.x * blockDim.x + threadIdx.x) >> 5;
    int lane = threadIdx.x & 31;
    const float* src; __half* dst; float* nrm; int row;
    if (warp < N_ROWS) { src = x; dst = g_hx; nrm = g_xnorm; row = warp; }
    else               { src = emb; dst = g_he; nrm = g_enorm; row = warp - N_ROWS; }
    const float4* p = reinterpret_cast<const float4*>(src + (size_t)row * DIM);
    uint2* o = reinterpret_cast<uint2*>(dst + (size_t)row * DIM);
    float s = 0.f;
    #pragma unroll
    for (int c = lane; c < DIM / 4; c += 32) {
        float4 v = p[c];
        s += v.x * v.x + v.y * v.y + v.z * v.z + v.w * v.w;
        __half2 lo = __floats2half2_rn(v.x, v.y);
        __half2 hi = __floats2half2_rn(v.z, v.w);
        uint2 u;
        u.x = *reinterpret_cast<unsigned*>(&lo);
        u.y = *reinterpret_cast<unsigned*>(&hi);
        o[c] = u;
    }
    #pragma unroll
    for (int off = 16; off; off >>= 1) s += __shfl_xor_sync(0xffffffffu, s, off);
    if (lane == 0) nrm[row] = s;
}

// fp16 HMMA GEMM: 128x128xK512 per CTA, 256 thr, 3-stage cp.async, ONE sync/stage.
// Epilogue: d~ = enorm - 2*dot, per-row min over 8-code chunks -> g_cmin (fp16).
__global__ void __launch_bounds__(256, 2) vq_gemm_kernel() {
    extern __shared__ __align__(1024) char smem[];
    const int tid = threadIdx.x;
    const int w = tid >> 5, l = tid & 31;
    const int rowBase = blockIdx.x * BM;
    const int cb = blockIdx.y * BN;
    const uint32_t sb = smem_u32(smem);
    float* senorm = reinterpret_cast<float*>(smem + SM_ENORM);

    if (tid < BN) senorm[tid] = g_enorm[cb + tid];

    // warp layout: 2 (M) x 4 (N); warp tile 64 x 32
    const int m0 = (w >> 2) * 64;
    const int n0 = (w & 3) * 32;
    const int aRowLane = l & 15;
    const int aChunkHi = l >> 4;
    const int bRowLane = ((l >> 4) & 1) * 8 + (l & 7);
    const int bChunkHi = (l >> 3) & 1;

    uint32_t c[4][4][2];
    #pragma unroll
    for (int mt = 0; mt < 4; mt++)
        #pragma unroll
        for (int nt = 0; nt < 4; nt++) { c[mt][nt][0] = 0u; c[mt][nt][1] = 0u; }

    auto load_stage = [&](int kc, int s) {
        const int kb = kc * KC;
        const uint32_t stg = sb + (uint32_t)s * STG_BYTES;
        #pragma unroll
        for (int q = 0; q < 4; q++) {
            int t = tid + q * 256;
            int r = t >> 3, ch = t & 7;
            cp16(stg + SWZ((uint32_t)(r * 128 + ch * 16)),
                 g_hx + (size_t)(rowBase + r) * DIM + kb + ch * 8);
        }
        #pragma unroll
        for (int q = 0; q < 4; q++) {
            int t = tid + q * 256;
            int r = t >> 3, ch = t & 7;
            cp16(stg + SM_BOFF + SWZ((uint32_t)(r * 128 + ch * 16)),
                 g_he + (size_t)(cb + r) * DIM + kb + ch * 8);
        }
        CP_COMMIT();
    };

    load_stage(0, 0);
    load_stage(1, 1);

    #pragma unroll
    for (int i = 0; i < NSTAGES; i++) {
        if (i < NSTAGES - 1) CP_WAIT(1); else CP_WAIT(0);
        __syncthreads();
        if (i + 2 < NSTAGES) load_stage(i + 2, (i + 2) % 3);
        const uint32_t aStg = sb + (uint32_t)(i % 3) * STG_BYTES;
        const uint32_t bStg = aStg + SM_BOFF;
        #pragma unroll
        for (int ks = 0; ks < 4; ks++) {
            uint32_t a[4][4], b[4][2];
            #pragma unroll
            for (int mt = 0; mt < 4; mt++) {
                uint32_t off = (uint32_t)((m0 + mt * 16 + aRowLane) * 128
                                          + (ks * 2 + aChunkHi) * 16);
                ldsm4(a[mt], aStg + SWZ(off));
            }
            #pragma unroll
            for (int nt2 = 0; nt2 < 2; nt2++) {
                uint32_t r4[4];
                uint32_t off = (uint32_t)((n0 + nt2 * 16 + bRowLane) * 128
                                          + (ks * 2 + bChunkHi) * 16);
                ldsm4(r4, bStg + SWZ(off));
                b[nt2 * 2][0] = r4[0]; b[nt2 * 2][1] = r4[1];
                b[nt2 * 2 + 1][0] = r4[2]; b[nt2 * 2 + 1][1] = r4[3];
            }
            #pragma unroll
            for (int mt = 0; mt < 4; mt++)
                #pragma unroll
                for (int nt = 0; nt < 4; nt++)
                    mma16816_h(c[mt][nt], a[mt], b[nt]);
        }
    }

    // ---- epilogue: chunk (8-code) mins -> smem staging -> coalesced fp16 gmem
    __syncthreads();
    float* sbuf = reinterpret_cast<float*>(smem);   // [128][20]

    #pragma unroll
    for (int mt = 0; mt < 4; mt++) {
        #pragma unroll
        for (int nt = 0; nt < 4; nt++) {
            const int colBase = n0 + nt * 8 + (l & 3) * 2;
            float en0 = senorm[colBase], en1 = senorm[colBase + 1];
            __half2 h0 = *reinterpret_cast<__half2*>(&c[mt][nt][0]);  // row r
            __half2 h1 = *reinterpret_cast<__half2*>(&c[mt][nt][1]);  // row r+8
            float v0 = fminf(en0 - 2.0f * __low2float(h0), en1 - 2.0f * __high2float(h0));
            float v1 = fminf(en0 - 2.0f * __low2float(h1), en1 - 2.0f * __high2float(h1));
            #pragma unroll
            for (int off = 1; off <= 2; off <<= 1) {
                v0 = fminf(v0, __shfl_xor_sync(0xffffffffu, v0, off));
                v1 = fminf(v1, __shfl_xor_sync(0xffffffffu, v1, off));
            }
            if ((l & 3) == 0) {
                int rloc = m0 + mt * 16 + (l >> 2);
                int chLoc = (w & 3) * 4 + nt;
                sbuf[rloc * 20 + chLoc] = v0;
                sbuf[(rloc + 8) * 20 + chLoc] = v1;
            }
        }
    }
    __syncthreads();
    {
        int row = tid >> 1, half = tid & 1;
        const float* s = &sbuf[row * 20 + half * 8];
        __half2 p0 = __floats2half2_rn(s[0], s[1]);
        __half2 p1 = __floats2half2_rn(s[2], s[3]);
        __half2 p2 = __floats2half2_rn(s[4], s[5]);
        __half2 p3 = __floats2half2_rn(s[6], s[7]);
        uint4 o;
        o.x = *reinterpret_cast<unsigned*>(&p0);
        o.y = *reinterpret_cast<unsigned*>(&p1);
        o.z = *reinterpret_cast<unsigned*>(&p2);
        o.w = *reinterpret_cast<unsigned*>(&p3);
        __half* dst = &g_cmin[(size_t)(blockIdx.x * BM + row) * NCH + blockIdx.y * 16 + half * 8];
        *reinterpret_cast<uint4*>(dst) = o;
    }
}

// warp-per-row streaming scan over fp16 g_cmin: min -> threshold -> compact
// candidate chunk ids. grid N_ROWS/8, block 256. No smem, no block syncs.
__global__ void __launch_bounds__(256) scan_kernel() {
    const int lane = threadIdx.x & 31;
    const int row = blockIdx.x * 8 + (threadIdx.x >> 5);

    const uint4* cm = reinterpret_cast<const uint4*>(&g_cmin[(size_t)row * NCH]);
    float2 f[4][4];
    float lmin = 3.4028235e38f;
    #pragma unroll
    for (int q = 0; q < 4; q++) {
        uint4 u = cm[lane + 32 * q];
        f[q][0] = __half22float2(*reinterpret_cast<__half2*>(&u.x));
        f[q][1] = __half22float2(*reinterpret_cast<__half2*>(&u.y));
        f[q][2] = __half22float2(*reinterpret_cast<__half2*>(&u.z));
        f[q][3] = __half22float2(*reinterpret_cast<__half2*>(&u.w));
        #pragma unroll
        for (int pj = 0; pj < 4; pj++)
            lmin = fminf(lmin, fminf(f[q][pj].x, f[q][pj].y));
    }
    #pragma unroll
    for (int off = 16; off; off >>= 1) lmin = fminf(lmin, __shfl_xor_sync(0xffffffffu, lmin, off));
    const float thr = lmin + EPS;

    int cnt = 0;
    int* cand = &g_cand[(size_t)row * MAXCAND];
    #pragma unroll
    for (int q = 0; q < 4; q++) {
        #pragma unroll
        for (int pj = 0; pj < 4; pj++) {
            #pragma unroll
            for (int e = 0; e < 2; e++) {
                float ve = e ? f[q][pj].y : f[q][pj].x;
                unsigned m = __ballot_sync(0xffffffffu, ve <= thr);
                if (m) {
                    if (ve <= thr) {
                        int rank = __popc(m & ((1u << lane) - 1));
                        int p = cnt + rank;
                        if (p < MAXCAND) cand[p] = (lane + 32 * q) * 8 + pj * 2 + e;
                    }
                    cnt += __popc(m);
                }
            }
        }
    }
    if (lane == 0) g_ccount[row] = min(cnt, MAXCAND);
}

// block-per-row exact rescore of candidate codes (flat-parallel across 8 warps,
// packed u64 keys for exact first-index tie-break) + fused gather/ST/rowsq.
__global__ void __launch_bounds__(256) rescore_kernel(const float* __restrict__ x,
                                                      const float* __restrict__ emb,
                                                      float* __restrict__ out) {
    __shared__ __align__(16) float sx[DIM];
    __shared__ float sred[8];
    __shared__ int   slist[MAXCAND];
    __shared__ unsigned long long skey[MAXCAND * CH];
    __shared__ int   sbesti;

    const int row = blockIdx.x;
    const int tid = threadIdx.x, w = tid >> 5, l = tid & 31;

    if (tid < 128)
        reinterpret_cast<float4*>(sx)[tid] =
            reinterpret_cast<const float4*>(x + (size_t)row * DIM)[tid];
    const int count = g_ccount[row];
    if (tid < count) slist[tid] = g_cand[(size_t)row * MAXCAND + tid];
    __syncthreads();

    const int ncodes = count * CH;
    const float xn = g_xnorm[row];

    for (int k = w; k < ncodes; k += 8) {
        const int code = slist[k >> 3] * CH + (k & 7);
        const float4* e4 = reinterpret_cast<const float4*>(emb + (size_t)code * DIM);
        const float4* xs = reinterpret_cast<const float4*>(sx);
        float acc = 0.f;
        #pragma unroll
        for (int t = 0; t < 4; t++) {
            float4 ev = e4[l + 32 * t];
            float4 xv = xs[l + 32 * t];
            acc = fmaf(ev.x, xv.x, acc);
            acc = fmaf(ev.y, xv.y, acc);
            acc = fmaf(ev.z, xv.z, acc);
            acc = fmaf(ev.w, xv.w, acc);
        }
        #pragma unroll
        for (int off = 16; off; off >>= 1) acc += __shfl_xor_sync(0xffffffffu, acc, off);
        if (l == 0) {
            float d = __fsub_rn(__fadd_rn(xn, g_enorm[code]), 2.0f * acc);
            skey[k] = ((unsigned long long)__float_as_uint(d) << 32) | (unsigned)code;
        }
    }
    __syncthreads();

    if (w == 0) {
        unsigned long long best = 0xffffffffffffffffull;
        for (int k = l; k < ncodes; k += 32) best = min(best, skey[k]);
        #pragma unroll
        for (int off = 16; off; off >>= 1) {
            unsigned long long o = __shfl_xor_sync(0xffffffffu, best, off);
            best = min(best, o);
        }
        if (l == 0) {
            int bi = (int)(best & 0xffffffffu);
            sbesti = bi;
            out[Q_ELEMS + 2 + row] = (float)bi;
            atomicMax(&g_maxidx, bi);
        }
    }
    __syncthreads();
    const int idx = sbesti;

    const float2* q2 = reinterpret_cast<const float2*>(emb + (size_t)idx * DIM);
    const float2* x2 = reinterpret_cast<const float2*>(sx);
    float2 qv = q2[tid], xv = x2[tid];
    float2 ov;
    float d0 = __fsub_rn(qv.x, xv.x); ov.x = __fadd_rn(xv.x, d0);
    float d1 = __fsub_rn(qv.y, xv.y); ov.y = __fadd_rn(xv.y, d1);
    reinterpret_cast<float2*>(out + (size_t)row * DIM)[tid] = ov;
    float ss = d0 * d0 + d1 * d1;
    #pragma unroll
    for (int off = 16; off; off >>= 1) ss += __shfl_xor_sync(0xffffffffu, ss, off);
    if (l == 0) sred[w] = ss;
    __syncthreads();
    if (tid == 0) {
        float t = 0.f;
        #pragma unroll
        for (int ww = 0; ww < 8; ww++) t += sred[ww];
        g_rowsq[row] = t;
    }
}

__global__ void scalars_kernel(float* __restrict__ out) {
    __shared__ float red[1024];
    const int tid = threadIdx.x;
    float s = 0.f;
    for (int r = tid; r < N_ROWS; r += 1024) s += g_rowsq[r];
    red[tid] = s;
    __syncthreads();
    #pragma unroll
    for (int st = 512; st > 0; st >>= 1) {
        if (tid < st) red[tid] += red[tid + st];
        __syncthreads();
    }
    if (tid == 0) {
        float mean = red[0] / (float)Q_ELEMS;
        out[Q_ELEMS] = 1.25f * mean;
        float L = (float)(g_maxidx + 1);
        float avg = 1.0f / L;
        out[Q_ELEMS + 1] = expf(-avg * logf(avg + 1e-10f));
    }
}

extern "C" void kernel_launch(void* const* d_in, const int* in_sizes, int n_in,
                              void* d_out, int out_size) {
    const float* x   = (const float*)d_in[0];
    const float* emb = (const float*)d_in[1];
    float* out = (float*)d_out;

    cudaFuncSetAttribute(vq_gemm_kernel, cudaFuncAttributeMaxDynamicSharedMemorySize, SM_TOTAL);

    init_kernel<<<1, 1>>>();
    convert_kernel<<<(N_ROWS + N_CODES) / 8, 256>>>(x, emb);
    vq_gemm_kernel<<<dim3(N_ROWS / BM, N_CODES / BN), 256, SM_TOTAL>>>();
    scan_kernel<<<N_ROWS / 8, 256>>>();
    rescore_kernel<<<N_ROWS, 256>>>(x, emb, out);
    scalars_kernel<<<1, 1024>>>(out);
}